// round 16
// baseline (speedup 1.0000x reference)
#include <cuda_runtime.h>
#include <cuda_bf16.h>

#define HH 256
#define WW 256
#define NMASK 64
#define CDIM 81
#define BQ 200
#define HW (HH*WW)
#define CEB 25          // CE blocks (8 rows each), appended to finish grid

// Device globals are zero-initialized at load; the pipeline is self-cleaning:
// finish_kernel re-zeros every slot it reads, and the last finish block resets
// the scalar accumulators. No init pass needed.
__device__ double g_acc[5];            // 2: pair sum, 3: tgt cnt, 4: proj sum
__device__ float  g_cepart[CEB * 2];   // per-CE-block (wnll, wsum) — plain stores
__device__ unsigned g_rowmax[NMASK * HH];
__device__ unsigned g_colmax[NMASK * WW];
__device__ int g_rowbox[NMASK * HH];
__device__ int g_colbox[NMASK * WW];
__device__ int g_done;

__device__ __forceinline__ unsigned fenc(float f) {
    unsigned u = __float_as_uint(f);
    return (u & 0x80000000u) ? ~u : (u | 0x80000000u);
}
__device__ __forceinline__ float fdec(unsigned u) {
    return (u & 0x80000000u) ? __uint_as_float(u & 0x7fffffffu) : __uint_as_float(~u);
}
// Fast softplus: 2 MUFU + few FMA. Abs err ~1e-7, fine vs 1e-3 tolerance.
__device__ __forceinline__ float softplusf(float z) {
    return fmaxf(z, 0.f) + __logf(1.f + __expf(-fabsf(z)));
}

// ---------------------------------------------------------------------------
// Fused pairwise + projection-max pass. Tile: 128 wide x 8 high per block
// (256 threads, 4 px/thread, 128-bit loads). sims float4s are converted to
// threshold bits IMMEDIATELY after load. Inner loop is a bit-walk over
// surviving (box & thresh & in-bounds) pairs; xc/spc cached in registers.
// sim = sp(xc)+sp(xn)-sp(xc+xn); OOB neighbors contribute exactly 0.
__global__ __launch_bounds__(256, 6)
void pair_kernel(const float* __restrict__ src,
                 const float* __restrict__ sims,
                 const int* __restrict__ box) {
    const int n = blockIdx.z;
    const int h0 = blockIdx.y * 8;
    const int w0 = blockIdx.x * 128;
    const int tx = threadIdx.x;       // 0..31
    const int ty = threadIdx.y;       // 0..7
    const int tid = ty * 32 + tx;

    __shared__ float sxf[12 * 132];   // src values, 2-px halo (flat)
    __shared__ float sspf[12 * 132];  // softplus(src)
    __shared__ int   sb[8][128];      // box tile
    __shared__ int   nboff[8];        // neighbor offsets in flat tile

    const int h = h0 + ty;
    const int wbase = w0 + tx * 4;

    if (tid < 8) {
        const int di[8] = {-2, -2, -2, 0, 0, 2, 2, 2};
        const int dj[8] = {-2, 0, 2, -2, 2, -2, 0, 2};
        nboff[tid] = di[tid] * 132 + dj[tid];
    }

    // Front-batched wide loads, converted to bits as they land.
    const float* simp = sims + (size_t)n * 8 * HW + h * WW + wbase;
    unsigned m = 0;
    #pragma unroll
    for (int p = 0; p < 8; p++) {
        float4 v = __ldcs((const float4*)(simp + (size_t)p * HW));
        m |= (v.x >= 0.3f ? 1u : 0u) << (0 * 8 + p);
        m |= (v.y >= 0.3f ? 1u : 0u) << (1 * 8 + p);
        m |= (v.z >= 0.3f ? 1u : 0u) << (2 * 8 + p);
        m |= (v.w >= 0.3f ? 1u : 0u) << (3 * 8 + p);
    }
    int4 b4 = __ldcs((const int4*)(box + (size_t)n * HW + h * WW + wbase));

    // Fill shared src tile (+ halo) and softplus.
    const float* srcn = src + (size_t)n * HW;
    for (int idx = tid; idx < 12 * 132; idx += 256) {
        int r = idx / 132, c = idx - r * 132;
        int gh = h0 - 2 + r, gw = w0 - 2 + c;
        float x = 0.f;
        if ((unsigned)gh < HH && (unsigned)gw < WW) x = srcn[gh * WW + gw];
        sxf[idx] = x;
        sspf[idx] = softplusf(x);
    }
    sb[ty][tx * 4 + 0] = b4.x;
    sb[ty][tx * 4 + 1] = b4.y;
    sb[ty][tx * 4 + 2] = b4.z;
    sb[ty][tx * 4 + 3] = b4.w;

    // Box gate (whole bytes) and tgt count (before OOB masking — reference
    // counts tgt over all taps including zero-padded ones).
    unsigned bm = (b4.x ? 0x000000FFu : 0u) | (b4.y ? 0x0000FF00u : 0u) |
                  (b4.z ? 0x00FF0000u : 0u) | (b4.w ? 0xFF000000u : 0u);
    m &= bm;
    float cnt = (float)__popc(m);
    int rbox = (b4.x | b4.y | b4.z | b4.w);

    // OOB allow-mask: only border threads lose bits.
    {
        unsigned rowbad = (h < 2 ? 0x07u : 0u) | (h > 253 ? 0xE0u : 0u);
        unsigned am = 0;
        #pragma unroll
        for (int i = 0; i < 4; i++) {
            int w = wbase + i;
            unsigned bad = rowbad | (w < 2 ? 0x29u : 0u) | (w > 253 ? 0x94u : 0u);
            am |= (0xFFu & ~bad) << (8 * i);
        }
        m &= am;
    }
    __syncthreads();

    // Cache center values/softplus in registers; row max from same loads.
    const int cbase = (ty + 2) * 132 + tx * 4 + 2;
    float xs[4], sps[4];
    float rmax = -1e30f;
    #pragma unroll
    for (int i = 0; i < 4; i++) {
        xs[i] = sxf[cbase + i];
        sps[i] = sspf[cbase + i];
        rmax = fmaxf(rmax, xs[i]);
    }

    // Bit-walk over surviving pairs.
    float sum = 0.f;
    while (m) {
        int b = __ffs(m) - 1;
        m &= m - 1;
        int i = b >> 3, p = b & 7;
        int off = nboff[p];
        float xc = xs[i];
        float spc = sps[i];
        float xn = sxf[cbase + i + off];
        float spn = sspf[cbase + i + off];
        float z = xc + xn;
        sum += spc + spn - (fmaxf(z, 0.f) + __logf(1.f + __expf(-fabsf(z))));
    }

    // Per-row (warp) reduce: pairwise sums + row max/box.
    #pragma unroll
    for (int o = 16; o > 0; o >>= 1) {
        sum += __shfl_down_sync(0xffffffff, sum, o);
        cnt += __shfl_down_sync(0xffffffff, cnt, o);
        rmax = fmaxf(rmax, __shfl_xor_sync(0xffffffff, rmax, o));
        rbox |= __shfl_xor_sync(0xffffffff, rbox, o);
    }
    if (tx == 0) {
        atomicMax(&g_rowmax[n * HH + h], fenc(rmax));
        if (rbox) g_rowbox[n * HH + h] = 1;   // idempotent store
    }

    // Column partials from the shared tile (threads 0..127, one column each).
    if (tid < 128) {
        const int c = tid;
        float mx = -1e30f; int ob = 0;
        #pragma unroll
        for (int r = 0; r < 8; r++) {
            mx = fmaxf(mx, sxf[(r + 2) * 132 + c + 2]);
            ob |= sb[r][c];
        }
        atomicMax(&g_colmax[n * WW + w0 + c], fenc(mx));
        if (ob) g_colbox[n * WW + w0 + c] = 1;
    }

    // Block reduce pairwise sums -> one double atomic each.
    __shared__ float rs[8], rc[8];
    if (tx == 0) { rs[ty] = sum; rc[ty] = cnt; }
    __syncthreads();
    if (tid == 0) {
        float S = 0.f, C = 0.f;
        #pragma unroll
        for (int i2 = 0; i2 < 8; i2++) { S += rs[i2]; C += rc[i2]; }
        atomicAdd(&g_acc[2], (double)S);
        atomicAdd(&g_acc[3], (double)C);
    }
}

// ---------------------------------------------------------------------------
// Finish: grid = 64 proj blocks + 25 CE blocks. Every block increments a
// completion counter; the LAST block (either kind) computes the output and
// resets the scalar accumulators. Proj blocks self-clean the max/box arrays.
__global__ void finish_kernel(const float* __restrict__ logits,
                              const int* __restrict__ cls,
                              const float* __restrict__ ew,
                              const int* __restrict__ num_masks_p,
                              float* __restrict__ out) {
    const int t = threadIdx.x;   // 0..255

    if (blockIdx.x >= NMASK) {
        // --- CE block: one row per warp, fully parallel ---
        const int b = blockIdx.x - NMASK;        // 0..24
        const int wid = t >> 5, lane = t & 31;
        const int row = b * 8 + wid;             // < 200
        const float* p = logits + row * CDIM;

        float v0 = p[lane];
        float v1 = p[lane + 32];
        float v2 = (lane < CDIM - 64) ? p[lane + 64] : -1e30f;
        float mx = fmaxf(v0, fmaxf(v1, v2));
        #pragma unroll
        for (int o = 16; o > 0; o >>= 1)
            mx = fmaxf(mx, __shfl_xor_sync(0xffffffff, mx, o));
        float se = __expf(v0 - mx) + __expf(v1 - mx) +
                   ((lane < CDIM - 64) ? __expf(v2 - mx) : 0.f);
        #pragma unroll
        for (int o = 16; o > 0; o >>= 1)
            se += __shfl_xor_sync(0xffffffff, se, o);

        __shared__ float s1[8], s2[8];
        if (lane == 0) {
            int tc = cls[row];
            float w = ew[tc];
            s1[wid] = -w * (p[tc] - mx - __logf(se));
            s2[wid] = w;
        }
        __syncthreads();
        if (t == 0) {
            float a = 0.f, bb = 0.f;
            #pragma unroll
            for (int i = 0; i < 8; i++) { a += s1[i]; bb += s2[i]; }
            g_cepart[b * 2 + 0] = a;
            g_cepart[b * 2 + 1] = bb;
            __threadfence();
            int prev = atomicAdd(&g_done, 1);
            if (prev == NMASK + CEB - 1) goto finalize;
        }
        return;

    } else {
        // --- Proj block: dice term for n, self-cleaning reads ---
        const int n = blockIdx.x;

        unsigned rm = g_rowmax[n * HH + t];
        int rb = g_rowbox[n * HH + t];
        unsigned cm = g_colmax[n * WW + t];
        int cb = g_colbox[n * WW + t];
        // Self-clean for next replay (stream-ordered before next pair pass).
        g_rowmax[n * HH + t] = 0u;  g_rowbox[n * HH + t] = 0;
        g_colmax[n * WW + t] = 0u;  g_colbox[n * WW + t] = 0;

        float ix = 1.f / (1.f + __expf(-fdec(rm)));
        float txv = (float)rb;
        float a0 = ix * txv, a1 = ix * ix, a2 = txv * txv;

        float iy = 1.f / (1.f + __expf(-fdec(cm)));
        float tyv = (float)cb;
        float b0 = iy * tyv, b1 = iy * iy, b2 = tyv * tyv;

        #pragma unroll
        for (int o = 16; o > 0; o >>= 1) {
            a0 += __shfl_down_sync(0xffffffff, a0, o);
            a1 += __shfl_down_sync(0xffffffff, a1, o);
            a2 += __shfl_down_sync(0xffffffff, a2, o);
            b0 += __shfl_down_sync(0xffffffff, b0, o);
            b1 += __shfl_down_sync(0xffffffff, b1, o);
            b2 += __shfl_down_sync(0xffffffff, b2, o);
        }
        __shared__ float r[6][8];
        int wid = t >> 5, lane = t & 31;
        if (lane == 0) {
            r[0][wid] = a0; r[1][wid] = a1; r[2][wid] = a2;
            r[3][wid] = b0; r[4][wid] = b1; r[5][wid] = b2;
        }
        __syncthreads();
        if (t == 0) {
            float s[6] = {0, 0, 0, 0, 0, 0};
            #pragma unroll
            for (int i = 0; i < 8; i++)
                #pragma unroll
                for (int k = 0; k < 6; k++) s[k] += r[k][i];
            double lx = 1.0 - 2.0 * (double)s[0] / ((double)s[1] + (double)s[2] + 1e-3);
            double ly = 1.0 - 2.0 * (double)s[3] / ((double)s[4] + (double)s[5] + 1e-3);
            atomicAdd(&g_acc[4], lx + ly);
            __threadfence();
            int prev = atomicAdd(&g_done, 1);
            if (prev == NMASK + CEB - 1) goto finalize;
        }
        return;
    }

finalize:
    {
        // Sum CE partials (unrolled independent loads, L2-resident).
        float cn = 0.f, cw = 0.f;
        #pragma unroll
        for (int i = 0; i < CEB; i++) {
            cn += g_cepart[i * 2 + 0];
            cw += g_cepart[i * 2 + 1];
        }
        int v = num_masks_p[0];
        if (v <= 0 || v > 1000000) {
            float f = __int_as_float(v);
            v = (int)f;
        }
        double nm = (double)max(v, 1);
        double ce = (double)cn / (double)cw;
        double pair = g_acc[2] / fmax(g_acc[3], 1.0) / nm;
        double proj = g_acc[4] / nm;
        out[0] = (float)(ce + pair + proj);
        // Reset scalar state for the next replay.
        g_acc[2] = 0.0; g_acc[3] = 0.0; g_acc[4] = 0.0;
        g_done = 0;
    }
}

// ---------------------------------------------------------------------------
extern "C" void kernel_launch(void* const* d_in, const int* in_sizes, int n_in,
                              void* d_out, int out_size) {
    const float* pred_logits = (const float*)d_in[0];   // (2,100,81)
    const float* src_masks   = (const float*)d_in[1];   // (64,256,256)
    const float* empty_w     = (const float*)d_in[2];   // (81,)
    const float* sims        = (const float*)d_in[3];   // (64,8,256,256)
    const int*   tgt_cls     = (const int*)d_in[4];     // (2,100)
    const int*   box         = (const int*)d_in[5];     // (64,256,256)
    const int*   num_masks   = (const int*)d_in[6];     // scalar
    float* out = (float*)d_out;

    pair_kernel<<<dim3(WW / 128, HH / 8, NMASK), dim3(32, 8)>>>(src_masks, sims, box);

    finish_kernel<<<NMASK + CEB, 256>>>(pred_logits, tgt_cls, empty_w,
                                        num_masks, out);
}

// round 17
// speedup vs baseline: 1.4721x; 1.4721x over previous
#include <cuda_runtime.h>
#include <cuda_bf16.h>

#define HH 256
#define WW 256
#define NMASK 64
#define CDIM 81
#define BQ 200
#define HW (HH*WW)
#define CEB 25          // CE blocks (8 rows each)
#define ZB 16           // zeroing blocks (uint4 stores)

// Accumulators (device globals; no mallocs allowed).
__device__ double g_acc[5];  // 2: pair sum, 3: tgt cnt, 4: proj sum
__device__ float  g_cepart[CEB * 2];   // per-CE-block (wnll, wsum) — plain stores
__device__ unsigned g_rowmax[NMASK * HH];
__device__ unsigned g_colmax[NMASK * WW];
__device__ int g_rowbox[NMASK * HH];
__device__ int g_colbox[NMASK * WW];
__device__ int g_done;

__device__ __forceinline__ unsigned fenc(float f) {
    unsigned u = __float_as_uint(f);
    return (u & 0x80000000u) ? ~u : (u | 0x80000000u);
}
__device__ __forceinline__ float fdec(unsigned u) {
    return (u & 0x80000000u) ? __uint_as_float(u & 0x7fffffffu) : __uint_as_float(~u);
}
// Fast softplus: 2 MUFU + few FMA. Abs err ~1e-7, fine vs 1e-3 tolerance.
__device__ __forceinline__ float softplusf(float z) {
    return fmaxf(z, 0.f) + __logf(1.f + __expf(-fabsf(z)));
}

// ---------------------------------------------------------------------------
// Fused init + cross-entropy. Grid (ZB + CEB) x 256:
//   blocks 0..ZB-1      : zero the row/col max/box arrays with uint4 stores
//   blocks ZB..ZB+CEB-1 : CE, one row per warp (no serial row loop)
__global__ void setup_kernel(const float* __restrict__ logits,
                             const int* __restrict__ cls,
                             const float* __restrict__ ew) {
    if (blockIdx.x < ZB) {
        // 16384 words per array; ZB*256 threads * 4 words = 16384.
        int i = blockIdx.x * 256 + threadIdx.x;   // 0..4095
        uint4 z4 = make_uint4(0u, 0u, 0u, 0u);
        ((uint4*)g_rowmax)[i] = z4;
        ((uint4*)g_colmax)[i] = z4;
        ((uint4*)g_rowbox)[i] = z4;
        ((uint4*)g_colbox)[i] = z4;
        if (blockIdx.x == 0 && threadIdx.x == 0) {
            g_acc[2] = 0.0; g_acc[3] = 0.0; g_acc[4] = 0.0; g_done = 0;
        }
        return;
    }

    // CE: one row per warp, fully parallel.
    const int b = blockIdx.x - ZB;               // 0..24
    const int wid = threadIdx.x >> 5, lane = threadIdx.x & 31;
    const int row = b * 8 + wid;                 // < 200
    const float* p = logits + row * CDIM;

    float v0 = p[lane];
    float v1 = p[lane + 32];
    float v2 = (lane < CDIM - 64) ? p[lane + 64] : -1e30f;
    float mx = fmaxf(v0, fmaxf(v1, v2));
    #pragma unroll
    for (int o = 16; o > 0; o >>= 1)
        mx = fmaxf(mx, __shfl_xor_sync(0xffffffff, mx, o));
    float se = __expf(v0 - mx) + __expf(v1 - mx) +
               ((lane < CDIM - 64) ? __expf(v2 - mx) : 0.f);
    #pragma unroll
    for (int o = 16; o > 0; o >>= 1)
        se += __shfl_xor_sync(0xffffffff, se, o);

    __shared__ float s1[8], s2[8];
    if (lane == 0) {
        int t = cls[row];
        float w = ew[t];
        s1[wid] = -w * (p[t] - mx - __logf(se));
        s2[wid] = w;
    }
    __syncthreads();
    if (threadIdx.x == 0) {
        float a = 0.f, bb = 0.f;
        #pragma unroll
        for (int i = 0; i < 8; i++) { a += s1[i]; bb += s2[i]; }
        g_cepart[b * 2 + 0] = a;
        g_cepart[b * 2 + 1] = bb;
    }
}

// ---------------------------------------------------------------------------
// Fused pairwise + projection-max pass. Tile: 128 wide x 8 high per block
// (256 threads, 4 px/thread, 128-bit loads). sims float4s are converted to
// threshold bits IMMEDIATELY after load (kills 32 regs of live payload ->
// higher occupancy). Inner loop is a bit-walk over surviving (box & thresh)
// pairs only. sim = sp(xc)+sp(xn)-sp(xc+xn); OOB neighbors contribute 0.
// NOTE: do NOT add live register state here — 6 blocks/SM caps regs at ~40
// and round-16 showed spills cost ~25us.
__global__ __launch_bounds__(256, 6)
void pair_kernel(const float* __restrict__ src,
                 const float* __restrict__ sims,
                 const int* __restrict__ box) {
    const int n = blockIdx.z;
    const int h0 = blockIdx.y * 8;
    const int w0 = blockIdx.x * 128;
    const int tx = threadIdx.x;       // 0..31
    const int ty = threadIdx.y;       // 0..7
    const int tid = ty * 32 + tx;

    __shared__ float sxf[12 * 132];   // src values, 2-px halo (flat)
    __shared__ float sspf[12 * 132];  // softplus(src)
    __shared__ int   sb[8][128];      // box tile
    __shared__ int   nboff[8];        // neighbor offsets in flat tile

    const int h = h0 + ty;
    const int wbase = w0 + tx * 4;

    if (tid < 8) {
        const int di[8] = {-2, -2, -2, 0, 0, 2, 2, 2};
        const int dj[8] = {-2, 0, 2, -2, 2, -2, 0, 2};
        nboff[tid] = di[tid] * 132 + dj[tid];
    }

    // Front-batched wide loads, converted to bits as they land.
    const float* simp = sims + (size_t)n * 8 * HW + h * WW + wbase;
    unsigned m = 0;
    #pragma unroll
    for (int p = 0; p < 8; p++) {
        float4 v = __ldcs((const float4*)(simp + (size_t)p * HW));
        m |= (v.x >= 0.3f ? 1u : 0u) << (0 * 8 + p);
        m |= (v.y >= 0.3f ? 1u : 0u) << (1 * 8 + p);
        m |= (v.z >= 0.3f ? 1u : 0u) << (2 * 8 + p);
        m |= (v.w >= 0.3f ? 1u : 0u) << (3 * 8 + p);
    }
    int4 b4 = __ldcs((const int4*)(box + (size_t)n * HW + h * WW + wbase));

    // Fill shared src tile (+ halo) and softplus.
    const float* srcn = src + (size_t)n * HW;
    for (int idx = tid; idx < 12 * 132; idx += 256) {
        int r = idx / 132, c = idx - r * 132;
        int gh = h0 - 2 + r, gw = w0 - 2 + c;
        float x = 0.f;
        if ((unsigned)gh < HH && (unsigned)gw < WW) x = srcn[gh * WW + gw];
        sxf[idx] = x;
        sspf[idx] = softplusf(x);
    }
    sb[ty][tx * 4 + 0] = b4.x;
    sb[ty][tx * 4 + 1] = b4.y;
    sb[ty][tx * 4 + 2] = b4.z;
    sb[ty][tx * 4 + 3] = b4.w;

    // Box gate (whole bytes) and tgt count (before OOB masking — reference
    // counts tgt over all taps including zero-padded ones).
    unsigned bm = (b4.x ? 0x000000FFu : 0u) | (b4.y ? 0x0000FF00u : 0u) |
                  (b4.z ? 0x00FF0000u : 0u) | (b4.w ? 0xFF000000u : 0u);
    m &= bm;
    float cnt = (float)__popc(m);
    int rbox = (b4.x | b4.y | b4.z | b4.w);

    // OOB allow-mask: only border threads lose bits.
    {
        unsigned rowbad = (h < 2 ? 0x07u : 0u) | (h > 253 ? 0xE0u : 0u);
        unsigned am = 0;
        #pragma unroll
        for (int i = 0; i < 4; i++) {
            int w = wbase + i;
            unsigned bad = rowbad | (w < 2 ? 0x29u : 0u) | (w > 253 ? 0x94u : 0u);
            am |= (0xFFu & ~bad) << (8 * i);
        }
        m &= am;
    }
    __syncthreads();

    // Bit-walk over surviving pairs.
    const int cbase = (ty + 2) * 132 + tx * 4 + 2;
    float sum = 0.f;
    float rmax = -1e30f;
    #pragma unroll
    for (int i = 0; i < 4; i++) rmax = fmaxf(rmax, sxf[cbase + i]);

    while (m) {
        int b = __ffs(m) - 1;
        m &= m - 1;
        int i = b >> 3, p = b & 7;
        int ci = cbase + i;
        int off = nboff[p];
        float xc = sxf[ci];
        float spc = sspf[ci];
        float xn = sxf[ci + off];
        float spn = sspf[ci + off];
        float z = xc + xn;
        sum += spc + spn - (fmaxf(z, 0.f) + __logf(1.f + __expf(-fabsf(z))));
    }

    // Per-row (warp) reduce: pairwise sums + row max/box.
    #pragma unroll
    for (int o = 16; o > 0; o >>= 1) {
        sum += __shfl_down_sync(0xffffffff, sum, o);
        cnt += __shfl_down_sync(0xffffffff, cnt, o);
        rmax = fmaxf(rmax, __shfl_xor_sync(0xffffffff, rmax, o));
        rbox |= __shfl_xor_sync(0xffffffff, rbox, o);
    }
    if (tx == 0) {
        atomicMax(&g_rowmax[n * HH + h], fenc(rmax));
        if (rbox) g_rowbox[n * HH + h] = 1;   // idempotent store
    }

    // Column partials from the shared tile (threads 0..127, one column each).
    if (tid < 128) {
        const int c = tid;
        float mx = -1e30f; int ob = 0;
        #pragma unroll
        for (int r = 0; r < 8; r++) {
            mx = fmaxf(mx, sxf[(r + 2) * 132 + c + 2]);
            ob |= sb[r][c];
        }
        atomicMax(&g_colmax[n * WW + w0 + c], fenc(mx));
        if (ob) g_colbox[n * WW + w0 + c] = 1;
    }

    // Block reduce pairwise sums -> one double atomic each.
    __shared__ float rs[8], rc[8];
    if (tx == 0) { rs[ty] = sum; rc[ty] = cnt; }
    __syncthreads();
    if (tid == 0) {
        float S = 0.f, C = 0.f;
        #pragma unroll
        for (int i2 = 0; i2 < 8; i2++) { S += rs[i2]; C += rc[i2]; }
        atomicAdd(&g_acc[2], (double)S);
        atomicAdd(&g_acc[3], (double)C);
    }
}

// ---------------------------------------------------------------------------
// Projection finish (64 blocks, one per n) with fused final: the LAST block
// to complete sums the CE partials and computes the output scalar.
__global__ void projfinish_kernel(const int* __restrict__ num_masks_p,
                                  float* __restrict__ out) {
    const int n = blockIdx.x;
    const int t = threadIdx.x;   // 0..255

    float mr = fdec(g_rowmax[n * HH + t]);
    float ix = 1.f / (1.f + __expf(-mr));
    float txv = (float)g_rowbox[n * HH + t];
    float a0 = ix * txv, a1 = ix * ix, a2 = txv * txv;

    float mc = fdec(g_colmax[n * WW + t]);
    float iy = 1.f / (1.f + __expf(-mc));
    float tyv = (float)g_colbox[n * WW + t];
    float b0 = iy * tyv, b1 = iy * iy, b2 = tyv * tyv;

    #pragma unroll
    for (int o = 16; o > 0; o >>= 1) {
        a0 += __shfl_down_sync(0xffffffff, a0, o);
        a1 += __shfl_down_sync(0xffffffff, a1, o);
        a2 += __shfl_down_sync(0xffffffff, a2, o);
        b0 += __shfl_down_sync(0xffffffff, b0, o);
        b1 += __shfl_down_sync(0xffffffff, b1, o);
        b2 += __shfl_down_sync(0xffffffff, b2, o);
    }
    __shared__ float r[6][8];
    int wid = t >> 5, lane = t & 31;
    if (lane == 0) {
        r[0][wid] = a0; r[1][wid] = a1; r[2][wid] = a2;
        r[3][wid] = b0; r[4][wid] = b1; r[5][wid] = b2;
    }
    __syncthreads();
    if (t == 0) {
        float s[6] = {0, 0, 0, 0, 0, 0};
        #pragma unroll
        for (int i = 0; i < 8; i++)
            #pragma unroll
            for (int k = 0; k < 6; k++) s[k] += r[k][i];
        double lx = 1.0 - 2.0 * (double)s[0] / ((double)s[1] + (double)s[2] + 1e-3);
        double ly = 1.0 - 2.0 * (double)s[3] / ((double)s[4] + (double)s[5] + 1e-3);
        atomicAdd(&g_acc[4], lx + ly);
        __threadfence();
        int prev = atomicAdd(&g_done, 1);
        if (prev == NMASK - 1) {
            // Sum CE partials (unrolled independent loads, L2-resident).
            float cn = 0.f, cw = 0.f;
            #pragma unroll
            for (int i = 0; i < CEB; i++) {
                cn += g_cepart[i * 2 + 0];
                cw += g_cepart[i * 2 + 1];
            }
            int v = num_masks_p[0];
            if (v <= 0 || v > 1000000) {
                float f = __int_as_float(v);
                v = (int)f;
            }
            double nm = (double)max(v, 1);
            double ce = (double)cn / (double)cw;
            double pair = g_acc[2] / fmax(g_acc[3], 1.0) / nm;
            double proj = g_acc[4] / nm;
            out[0] = (float)(ce + pair + proj);
        }
    }
}

// ---------------------------------------------------------------------------
extern "C" void kernel_launch(void* const* d_in, const int* in_sizes, int n_in,
                              void* d_out, int out_size) {
    const float* pred_logits = (const float*)d_in[0];   // (2,100,81)
    const float* src_masks   = (const float*)d_in[1];   // (64,256,256)
    const float* empty_w     = (const float*)d_in[2];   // (81,)
    const float* sims        = (const float*)d_in[3];   // (64,8,256,256)
    const int*   tgt_cls     = (const int*)d_in[4];     // (2,100)
    const int*   box         = (const int*)d_in[5];     // (64,256,256)
    const int*   num_masks   = (const int*)d_in[6];     // scalar
    float* out = (float*)d_out;

    setup_kernel<<<ZB + CEB, 256>>>(pred_logits, tgt_cls, empty_w);

    pair_kernel<<<dim3(WW / 128, HH / 8, NMASK), dim3(32, 8)>>>(src_masks, sims, box);

    projfinish_kernel<<<NMASK, 256>>>(num_masks, out);
}